// round 5
// baseline (speedup 1.0000x reference)
#include <cuda_runtime.h>
#include <cstdint>

#define D_FEAT          128
#define N_EDGES_MAX     50008
#define WARPS_PER_BLOCK 8
#define BATCH           4     // rows per pipeline stage
#define STAGES          2
#define ROW_BYTES       512   // 128 * 4B

// Scratch: segment start offsets
__device__ int d_seg_start[N_EDGES_MAX + 1];

// ---------------------------------------------------------------------------
// Kernel 1: run-boundary detection on the sorted segment_ids (int32).
// ---------------------------------------------------------------------------
__global__ void offsets_kernel(const int* __restrict__ seg_ids,
                               int flat, int n_edges) {
    int i = blockIdx.x * blockDim.x + threadIdx.x;
    if (i >= flat) return;
    int cur  = __ldg(&seg_ids[i]);
    int prev = (i == 0) ? -1 : __ldg(&seg_ids[i - 1]);
    for (int e = prev + 1; e <= cur; e++)
        d_seg_start[e] = i;
    if (i == flat - 1) {
        for (int e = cur + 1; e <= n_edges; e++)
            d_seg_start[e] = flat;
    }
}

// ---------------------------------------------------------------------------
// Async-proxy helpers
// ---------------------------------------------------------------------------
__device__ __forceinline__ uint32_t smem_u32(const void* p) {
    return (uint32_t)__cvta_generic_to_shared(p);
}

__device__ __forceinline__ void mbar_init(uint32_t mb, int count) {
    asm volatile("mbarrier.init.shared::cta.b64 [%0], %1;"
                 :: "r"(mb), "r"(count) : "memory");
}

__device__ __forceinline__ void mbar_expect_tx(uint32_t mb, int bytes) {
    asm volatile("mbarrier.arrive.expect_tx.shared::cta.b64 _, [%0], %1;"
                 :: "r"(mb), "r"(bytes) : "memory");
}

__device__ __forceinline__ void bulk_copy_row(uint32_t dst, const float* src,
                                              uint32_t mb) {
    asm volatile(
        "cp.async.bulk.shared::cta.global.mbarrier::complete_tx::bytes "
        "[%0], [%1], %2, [%3];"
        :: "r"(dst), "l"(src), "r"(ROW_BYTES), "r"(mb) : "memory");
}

__device__ __forceinline__ void mbar_wait(uint32_t mb, int phase) {
    asm volatile(
        "{\n\t"
        ".reg .pred P;\n\t"
        "W_%=:\n\t"
        "mbarrier.try_wait.parity.acquire.cta.shared::cta.b64 P, [%0], %1, 0x989680;\n\t"
        "@P bra D_%=;\n\t"
        "bra.uni W_%=;\n\t"
        "D_%=:\n\t"
        "}"
        :: "r"(mb), "r"(phase) : "memory");
}

// ---------------------------------------------------------------------------
// Kernel 2: warp-per-segment segment-max with a 2-stage cp.async.bulk pipeline.
// Row fetches go global->SMEM through the async proxy (bypassing the L1tex
// global-load return path); consumption is conflict-free LDS.128 + fmax.
// Ragged tails are padded with the last member's row (max is idempotent).
// ---------------------------------------------------------------------------
__global__ void __launch_bounds__(WARPS_PER_BLOCK * 32)
seg_max_kernel(const float* __restrict__ emb,       // [N_NODES * 128]
               const int* __restrict__ node_idx,
               float4* __restrict__ out,            // [n_edges * 32] float4
               int n_edges) {
    __shared__ float4 buf[WARPS_PER_BLOCK][STAGES][BATCH][32];   // 32 KB
    __shared__ unsigned long long mbar[WARPS_PER_BLOCK][STAGES];

    int wib   = threadIdx.x >> 5;
    int lane  = threadIdx.x & 31;
    int gwarp = (blockIdx.x * blockDim.x + threadIdx.x) >> 5;

    if (lane == 0) {
        mbar_init(smem_u32(&mbar[wib][0]), 1);
        mbar_init(smem_u32(&mbar[wib][1]), 1);
        asm volatile("fence.proxy.async.shared::cta;" ::: "memory");
    }
    __syncwarp();

    if (gwarp >= n_edges) return;

    int start = d_seg_start[gwarp];
    int end   = d_seg_start[gwarp + 1];

    if (start >= end) {                    // empty segment -> zeros
        out[(size_t)gwarp * 32 + lane] = make_float4(0.f, 0.f, 0.f, 0.f);
        return;
    }

    int last   = end - 1;
    int cnt    = end - start;
    int nbatch = (cnt + BATCH - 1) / BATCH;

    // Issue one 4-row batch into stage s (indices fetched by lanes 0..3,
    // copies issued by lane 0).
    auto issue = [&](int b, int s) {
        int li = start + b * BATCH + lane;
        int nd_l = 0;
        if (lane < BATCH)
            nd_l = __ldg(&node_idx[li <= last ? li : last]);
        int n0 = __shfl_sync(0xffffffffu, nd_l, 0);
        int n1 = __shfl_sync(0xffffffffu, nd_l, 1);
        int n2 = __shfl_sync(0xffffffffu, nd_l, 2);
        int n3 = __shfl_sync(0xffffffffu, nd_l, 3);
        if (lane == 0) {
            uint32_t mb = smem_u32(&mbar[wib][s]);
            mbar_expect_tx(mb, BATCH * ROW_BYTES);
            uint32_t d = smem_u32(&buf[wib][s][0][0]);
            bulk_copy_row(d + 0 * ROW_BYTES, emb + (size_t)n0 * D_FEAT, mb);
            bulk_copy_row(d + 1 * ROW_BYTES, emb + (size_t)n1 * D_FEAT, mb);
            bulk_copy_row(d + 2 * ROW_BYTES, emb + (size_t)n2 * D_FEAT, mb);
            bulk_copy_row(d + 3 * ROW_BYTES, emb + (size_t)n3 * D_FEAT, mb);
        }
    };

    issue(0, 0);
    if (nbatch > 1) issue(1, 1);

    const float NEG = -3.402823466e+38f;
    float4 acc = make_float4(NEG, NEG, NEG, NEG);
    int ph0 = 0, ph1 = 0;

    for (int b = 0; b < nbatch; b++) {
        int s = b & 1;
        uint32_t mb = smem_u32(&mbar[wib][s]);
        int ph = s ? ph1 : ph0;
        mbar_wait(mb, ph);
        if (s) ph1 ^= 1; else ph0 ^= 1;

        #pragma unroll
        for (int k = 0; k < BATCH; k++) {
            float4 v = buf[wib][s][k][lane];     // conflict-free LDS.128
            acc.x = fmaxf(acc.x, v.x);
            acc.y = fmaxf(acc.y, v.y);
            acc.z = fmaxf(acc.z, v.z);
            acc.w = fmaxf(acc.w, v.w);
        }

        __syncwarp();
        // order this warp's LDS reads before the async-proxy refill writes
        asm volatile("fence.proxy.async.shared::cta;" ::: "memory");
        if (b + 2 < nbatch) issue(b + 2, s);
    }

    out[(size_t)gwarp * 32 + lane] = acc;
}

// ---------------------------------------------------------------------------
// Launch
// inputs: emb_table f32 [100000,128], node_idx i32 [1.6M],
//         segment_ids i32 [1.6M], num_segments scalar
// output: f32 [50000,128]
// ---------------------------------------------------------------------------
extern "C" void kernel_launch(void* const* d_in, const int* in_sizes, int n_in,
                              void* d_out, int out_size) {
    const float* emb      = (const float*)d_in[0];
    const int*   node_idx = (const int*)d_in[1];
    const int*   seg_ids  = (const int*)d_in[2];
    float4*      out      = (float4*)d_out;

    int flat    = in_sizes[1];            // 1,600,000
    int n_edges = out_size / D_FEAT;      // 50,000

    {
        int threads = 256;
        int blocks  = (flat + threads - 1) / threads;
        offsets_kernel<<<blocks, threads>>>(seg_ids, flat, n_edges);
    }
    {
        int threads = WARPS_PER_BLOCK * 32;   // 256
        int blocks  = (n_edges + WARPS_PER_BLOCK - 1) / WARPS_PER_BLOCK;
        seg_max_kernel<<<blocks, threads>>>(emb, node_idx, out, n_edges);
    }
}

// round 6
// speedup vs baseline: 1.4847x; 1.4847x over previous
#include <cuda_runtime.h>
#include <cstdint>

#define D_FEAT      128
#define N_EDGES_MAX 50008

// Scratch: segment start offsets (d_seg_start[e] = first flat index with seg id >= e)
__device__ int d_seg_start[N_EDGES_MAX + 1];

// ---------------------------------------------------------------------------
// Kernel 1: run-boundary detection on sorted segment_ids (int32).
// Each thread loads ONE element; the left neighbor comes from __shfl_up
// (lane 0 loads it directly). Halves the read traffic of the naive version.
// ---------------------------------------------------------------------------
__global__ void offsets_kernel(const int* __restrict__ seg_ids,
                               int flat, int n_edges) {
    int i = blockIdx.x * blockDim.x + threadIdx.x;
    int lane = threadIdx.x & 31;

    int cur = (i < flat) ? __ldg(&seg_ids[i]) : 0x7fffffff;
    int prev = __shfl_up_sync(0xffffffffu, cur, 1);
    if (lane == 0)
        prev = (i == 0) ? -1 : ((i <= flat) ? __ldg(&seg_ids[i - 1]) : 0x7fffffff);

    if (i < flat) {
        for (int e = prev + 1; e <= cur; e++)     // usually 0 or 1 iterations
            d_seg_start[e] = i;
        if (i == flat - 1) {
            for (int e = cur + 1; e <= n_edges; e++)
                d_seg_start[e] = flat;
        }
    }
}

// ---------------------------------------------------------------------------
// Kernel 2: warp-per-segment ragged segment-max (R2 champion shape).
// Each lane owns one float4 (4 of 128 feats); member indices are fetched
// coalesced 32-ahead and shfl-broadcast; the loop body's only memory op is
// the coalesced 512B row load. This sits at the chip LTS service cap.
// ---------------------------------------------------------------------------
__global__ void __launch_bounds__(256)
seg_max_kernel(const float4* __restrict__ emb,      // [N_NODES * 32] float4
               const int* __restrict__ node_idx,
               float4* __restrict__ out,            // [n_edges * 32] float4
               int n_edges) {
    int gwarp = (blockIdx.x * blockDim.x + threadIdx.x) >> 5;
    int lane  = threadIdx.x & 31;
    if (gwarp >= n_edges) return;

    int start = d_seg_start[gwarp];
    int end   = d_seg_start[gwarp + 1];

    float4 acc = make_float4(0.f, 0.f, 0.f, 0.f);   // empty segment -> zeros

    if (start < end) {
        const float NEG = -3.402823466e+38f;
        acc = make_float4(NEG, NEG, NEG, NEG);
        const float4* embl = emb + lane;
        int last = end - 1;

        for (int base = start; base < end; base += 32) {
            int li = base + lane;
            int nd_l = __ldg(&node_idx[li <= last ? li : last]);  // clamped, coalesced
            int cnt = end - base;
            if (cnt > 32) cnt = 32;

            #pragma unroll 4
            for (int j = 0; j < cnt; j++) {
                int nd = __shfl_sync(0xffffffffu, nd_l, j);
                float4 v = __ldg(embl + (size_t)nd * 32);
                acc.x = fmaxf(acc.x, v.x);
                acc.y = fmaxf(acc.y, v.y);
                acc.z = fmaxf(acc.z, v.z);
                acc.w = fmaxf(acc.w, v.w);
            }
        }
    }

    out[(size_t)gwarp * 32 + lane] = acc;
}

// ---------------------------------------------------------------------------
// Launch
// inputs: emb_table f32 [100000,128], node_idx i32 [1.6M],
//         segment_ids i32 [1.6M], num_segments scalar
// output: f32 [50000,128]
// ---------------------------------------------------------------------------
extern "C" void kernel_launch(void* const* d_in, const int* in_sizes, int n_in,
                              void* d_out, int out_size) {
    const float4* emb      = (const float4*)d_in[0];
    const int*    node_idx = (const int*)d_in[1];
    const int*    seg_ids  = (const int*)d_in[2];
    float4*       out      = (float4*)d_out;

    int flat    = in_sizes[1];            // 1,600,000
    int n_edges = out_size / D_FEAT;      // 50,000

    {
        int threads = 256;
        int blocks  = (flat + threads) / threads;   // cover i == flat boundary
        offsets_kernel<<<blocks, threads>>>(seg_ids, flat, n_edges);
    }
    {
        int threads = 256;                 // 8 warps = 8 segments / block
        int blocks  = (n_edges * 32 + threads - 1) / threads;
        seg_max_kernel<<<blocks, threads>>>(emb, node_idx, out, n_edges);
    }
}